// round 14
// baseline (speedup 1.0000x reference)
#include <cuda_runtime.h>
#include <cuda_bf16.h>
#include <cstdint>

#define BB 32
#define TT 256
#define DD 512
#define PP 20
#define EPSV 1e-12f

// ---------------- scratch (__device__ globals; no cudaMalloc allowed) ------
__device__ __align__(16) __nv_bfloat16 g_nbn_bf [BB * TT * DD];   // [b][t][d]
__device__ __align__(16) __nv_bfloat16 g_nbnT_bf[BB * DD * TT];   // [b][d][t]
__device__ __align__(16) __nv_bfloat16 g_nanT_bf[BB * DD * TT];   // [b][d][t]
__device__ __align__(16) __nv_bfloat16 g_alphaTb[(size_t)BB * DD * DD]; // [b][e][d]
__device__ __align__(16) float g_colpart[BB * 4 * DD];            // per (b, mtile, e)
__device__ __align__(16) __nv_bfloat16 g_hmean_bf[BB * TT * DD];  // [b][t][e]
__device__ __align__(16) __nv_bfloat16 g_W2bf[24 * 520];          // W^2, padded

__device__ __forceinline__ uint32_t smem_u32(const void* p) {
    return (uint32_t)__cvta_generic_to_shared(p);
}
// pack two fp32 -> bf16x2 (lo = x, hi = y), round-to-nearest-even
__device__ __forceinline__ uint32_t pack_bf2(float x, float y) {
    uint32_t r;
    asm("cvt.rn.bf16x2.f32 %0, %1, %2;" : "=r"(r) : "f"(y), "f"(x));
    return r;
}

// ---------------------------------------------------------------------------
// Kernel 1: row l2-normalize + transpose, bf16 outputs.
// ---------------------------------------------------------------------------
__global__ void __launch_bounds__(256) k_normT(const float* __restrict__ a,
                                               const float* __restrict__ b) {
    __shared__ float s[16 * 513];
    __shared__ float sinv[16];
    int which = blockIdx.z;
    int bb = blockIdx.y;
    int t0 = blockIdx.x * 16;
    const float* src = (which ? b : a) + ((size_t)bb * TT + t0) * DD;
    int tid = threadIdx.x;

#pragma unroll
    for (int i = 0; i < 8; i++) {
        int idx = tid + i * 256;
        int r = idx >> 7, c4 = idx & 127;
        float4 v = *(const float4*)(src + (size_t)r * DD + c4 * 4);
        float* sr = s + r * 513 + c4 * 4;
        sr[0] = v.x; sr[1] = v.y; sr[2] = v.z; sr[3] = v.w;
    }
    __syncthreads();

    int wid = tid >> 5, lid = tid & 31;
#pragma unroll
    for (int rr = 0; rr < 2; rr++) {
        int r = wid * 2 + rr;
        float ss = 0.f;
#pragma unroll
        for (int j = 0; j < 16; j++) { float v = s[r * 513 + lid + 32 * j]; ss += v * v; }
#pragma unroll
        for (int o = 16; o > 0; o >>= 1) ss += __shfl_xor_sync(0xffffffffu, ss, o);
        if (lid == 0) sinv[r] = rsqrtf(fmaxf(ss, EPSV));
    }
    __syncthreads();

    __nv_bfloat16* dstT = (which ? g_nbnT_bf : g_nanT_bf) + (size_t)bb * DD * TT;
#pragma unroll
    for (int i = 0; i < 8; i++) {
        int idx = tid + i * 256;
        int d = idx >> 2, jq = (idx & 3) * 4;
        float o0 = s[(jq + 0) * 513 + d] * sinv[jq + 0];
        float o1 = s[(jq + 1) * 513 + d] * sinv[jq + 1];
        float o2 = s[(jq + 2) * 513 + d] * sinv[jq + 2];
        float o3 = s[(jq + 3) * 513 + d] * sinv[jq + 3];
        uint2 u = make_uint2(pack_bf2(o0, o1), pack_bf2(o2, o3));
        *(uint2*)(dstT + (size_t)d * TT + t0 + jq) = u;
    }
    if (which) {
        __nv_bfloat16* dst = g_nbn_bf + ((size_t)bb * TT + t0) * DD;
#pragma unroll
        for (int i = 0; i < 8; i++) {
            int idx = tid + i * 256;
            int r = idx >> 7, c4 = idx & 127;
            float inv = sinv[r];
            float* sr = s + r * 513 + c4 * 4;
            uint2 u = make_uint2(pack_bf2(sr[0] * inv, sr[1] * inv),
                                 pack_bf2(sr[2] * inv, sr[3] * inv));
            *(uint2*)(dst + (size_t)r * DD + c4 * 4) = u;
        }
    }
}

// ---------------------------------------------------------------------------
// bf16 mma.sync GEMM, 4-stage cp.async pipeline, one barrier per K-chunk.
// CTA tile 128x128, K-chunk 32. Store transposed: C[n*512 + m], bf16.
// mode 1 (GEMM1): also emit per-CTA column sum-of-squares partials
// mode 2 (GEMM2): scale output by rsqrt(max(sum_j colpart[j][m], eps))
// ---------------------------------------------------------------------------
__global__ void __launch_bounds__(256, 2) k_gemm_bf16(
    const __nv_bfloat16* __restrict__ Ag, int lda, size_t strideA,
    const __nv_bfloat16* __restrict__ Bg, int ldb, size_t strideB,
    __nv_bfloat16* __restrict__ Cg, size_t strideC,
    float* __restrict__ colpart, int Ktot, int mode) {
    __shared__ __align__(16) char sm[4 * 16384];  // 64KB

    int b = blockIdx.z;
    int m0 = blockIdx.x * 128, n0 = blockIdx.y * 128;
    const __nv_bfloat16* A  = Ag + (size_t)b * strideA + (size_t)m0 * lda;
    const __nv_bfloat16* Bp = Bg + (size_t)b * strideB + (size_t)n0 * ldb;

    int tid = threadIdx.x, lane = tid & 31, wid = tid >> 5;
    int wm = wid & 1, wn = wid >> 1;
    uint32_t smbase = smem_u32(sm);

    float acc[4][4][4];
#pragma unroll
    for (int i = 0; i < 4; i++)
#pragma unroll
        for (int j = 0; j < 4; j++)
#pragma unroll
            for (int k = 0; k < 4; k++) acc[i][j][k] = 0.f;

    int nkt = Ktot / 32;

    auto issue_chunk = [&](int kt) {
        uint32_t base = smbase + (uint32_t)(kt & 3) * 16384u;
        int k0 = kt * 32;
#pragma unroll
        for (int i = 0; i < 2; i++) {
            int idx = tid + i * 256;
            int r = idx >> 2, q = idx & 3;
            uint32_t off = (uint32_t)(r * 64 + ((q ^ ((r >> 1) & 3)) << 4));
            const __nv_bfloat16* srcA = A + (size_t)r * lda + k0 + q * 8;
            asm volatile("cp.async.cg.shared.global [%0], [%1], 16;"
                         :: "r"(base + off), "l"(srcA));
            const __nv_bfloat16* srcB = Bp + (size_t)r * ldb + k0 + q * 8;
            asm volatile("cp.async.cg.shared.global [%0], [%1], 16;"
                         :: "r"(base + 8192u + off), "l"(srcB));
        }
        asm volatile("cp.async.commit_group;");
    };

    issue_chunk(0);
    issue_chunk(1);
    issue_chunk(2);

    for (int kt = 0; kt < nkt; kt++) {
        asm volatile("cp.async.wait_group 2;" ::: "memory");
        __syncthreads();
        if (kt + 3 < nkt) issue_chunk(kt + 3);

        uint32_t baseA = smbase + (uint32_t)(kt & 3) * 16384u;
        uint32_t baseB = baseA + 8192u;

#pragma unroll
        for (int ks = 0; ks < 2; ks++) {
            uint32_t af[4][4], bf[4][2];
#pragma unroll
            for (int mt = 0; mt < 4; mt++) {
                int r = wm * 64 + mt * 16 + (lane & 15);
                int q = ks * 2 + (lane >> 4);
                uint32_t addr = baseA + (uint32_t)(r * 64 + ((q ^ ((r >> 1) & 3)) << 4));
                asm volatile("ldmatrix.sync.aligned.m8n8.x4.shared.b16 {%0,%1,%2,%3}, [%4];"
                             : "=r"(af[mt][0]), "=r"(af[mt][1]),
                               "=r"(af[mt][2]), "=r"(af[mt][3])
                             : "r"(addr));
            }
#pragma unroll
            for (int nt = 0; nt < 4; nt++) {
                int r = wn * 32 + nt * 8 + (lane & 7);
                int q = ks * 2 + ((lane >> 3) & 1);
                uint32_t addr = baseB + (uint32_t)(r * 64 + ((q ^ ((r >> 1) & 3)) << 4));
                asm volatile("ldmatrix.sync.aligned.m8n8.x2.shared.b16 {%0,%1}, [%2];"
                             : "=r"(bf[nt][0]), "=r"(bf[nt][1])
                             : "r"(addr));
            }
#pragma unroll
            for (int mt = 0; mt < 4; mt++)
#pragma unroll
                for (int nt = 0; nt < 4; nt++) {
                    asm volatile(
                        "mma.sync.aligned.m16n8k16.row.col.f32.bf16.bf16.f32 "
                        "{%0,%1,%2,%3}, {%4,%5,%6,%7}, {%8,%9}, {%0,%1,%2,%3};"
                        : "+f"(acc[mt][nt][0]), "+f"(acc[mt][nt][1]),
                          "+f"(acc[mt][nt][2]), "+f"(acc[mt][nt][3])
                        : "r"(af[mt][0]), "r"(af[mt][1]),
                          "r"(af[mt][2]), "r"(af[mt][3]),
                          "r"(bf[nt][0]), "r"(bf[nt][1]));
                }
        }
    }

    // ---- epilogue ----
    __nv_bfloat16* Cb = Cg + (size_t)b * strideC;

    if (mode == 1) {
#pragma unroll
        for (int mt = 0; mt < 4; mt++) {
            int r0 = m0 + wm * 64 + mt * 16 + (lane >> 2);
#pragma unroll
            for (int nt = 0; nt < 4; nt++) {
                int c0 = n0 + wn * 32 + nt * 8 + (lane & 3) * 2;
                Cb[(size_t)c0 * 512 + r0]           = __float2bfloat16(acc[mt][nt][0]);
                Cb[(size_t)(c0 + 1) * 512 + r0]     = __float2bfloat16(acc[mt][nt][1]);
                Cb[(size_t)c0 * 512 + r0 + 8]       = __float2bfloat16(acc[mt][nt][2]);
                Cb[(size_t)(c0 + 1) * 512 + r0 + 8] = __float2bfloat16(acc[mt][nt][3]);
            }
        }
        float p0[4], p1[4];
#pragma unroll
        for (int nt = 0; nt < 4; nt++) {
            float s0 = 0.f, s1 = 0.f;
#pragma unroll
            for (int mt = 0; mt < 4; mt++) {
                s0 += acc[mt][nt][0] * acc[mt][nt][0] + acc[mt][nt][2] * acc[mt][nt][2];
                s1 += acc[mt][nt][1] * acc[mt][nt][1] + acc[mt][nt][3] * acc[mt][nt][3];
            }
#pragma unroll
            for (int o = 4; o < 32; o <<= 1) {
                s0 += __shfl_xor_sync(0xffffffffu, s0, o);
                s1 += __shfl_xor_sync(0xffffffffu, s1, o);
            }
            p0[nt] = s0; p1[nt] = s1;
        }
        __syncthreads();
        float* psum = (float*)sm;
        if (wm == 0 && lane < 4) {
#pragma unroll
            for (int nt = 0; nt < 4; nt++) {
                int idx = wn * 32 + nt * 8 + lane * 2;
                psum[idx] = p0[nt]; psum[idx + 1] = p1[nt];
            }
        }
        __syncthreads();
        if (wm == 1 && lane < 4) {
#pragma unroll
            for (int nt = 0; nt < 4; nt++) {
                int idx = wn * 32 + nt * 8 + lane * 2;
                psum[idx] += p0[nt]; psum[idx + 1] += p1[nt];
            }
        }
        __syncthreads();
        if (tid < 128)
            colpart[((size_t)b * 4 + blockIdx.x) * DD + n0 + tid] = psum[tid];
    } else {
        const float* cp = colpart + (size_t)b * 4 * DD;
#pragma unroll
        for (int mt = 0; mt < 4; mt++) {
            int r0 = m0 + wm * 64 + mt * 16 + (lane >> 2);
            float cs0 = cp[r0] + cp[DD + r0] + cp[2 * DD + r0] + cp[3 * DD + r0];
            float cs1 = cp[r0 + 8] + cp[DD + r0 + 8] + cp[2 * DD + r0 + 8] + cp[3 * DD + r0 + 8];
            float sc0 = rsqrtf(fmaxf(cs0, EPSV));
            float sc1 = rsqrtf(fmaxf(cs1, EPSV));
#pragma unroll
            for (int nt = 0; nt < 4; nt++) {
                int c0 = n0 + wn * 32 + nt * 8 + (lane & 3) * 2;
                Cb[(size_t)c0 * 512 + r0]           = __float2bfloat16(acc[mt][nt][0] * sc0);
                Cb[(size_t)(c0 + 1) * 512 + r0]     = __float2bfloat16(acc[mt][nt][1] * sc0);
                Cb[(size_t)c0 * 512 + r0 + 8]       = __float2bfloat16(acc[mt][nt][2] * sc1);
                Cb[(size_t)(c0 + 1) * 512 + r0 + 8] = __float2bfloat16(acc[mt][nt][3] * sc1);
            }
        }
    }
}

// ---------------------------------------------------------------------------
// W^2 prepack: g_W2bf[24][520] bf16, zero-padded beyond (20, 512).
// ---------------------------------------------------------------------------
__global__ void k_w2(const float* __restrict__ W) {
    int i = blockIdx.x * blockDim.x + threadIdx.x;
    if (i >= 24 * 520) return;
    int p = i / 520, d = i - p * 520;
    float v = 0.f;
    if (p < PP && d < DD) { float w = W[p * DD + d]; v = w * w; }
    g_W2bf[i] = __float2bfloat16(v);
}

// ---------------------------------------------------------------------------
// Perspective via tensor cores.
// S_k[row,p] = sum_d P_k[row,d] * W2[p,d], P1=a*a, P2=h*h, P3=a*h.
// Block: 128 thr (4 warps), 64 rows, N=24 (3 n8 tiles), K-chunk 32.
// Products computed fp32 -> one bf16 rounding -> swizzled smem -> ldmatrix.
// Epilogue elementwise on fragments: persp = S3*rsqrt(S1)*rsqrt(S2).
// ---------------------------------------------------------------------------
__global__ void __launch_bounds__(128) k_persp2(const float* __restrict__ inp_a,
                                                float* __restrict__ out, int dup) {
    __shared__ __align__(16) __nv_bfloat16 sW2[24 * 520];   // 24.4KB, rows 1040B
    __shared__ __align__(16) __nv_bfloat16 sP[3][64 * 32];  // 12KB, rows 64B swizzled

    int tid = threadIdx.x, lane = tid & 31, w = tid >> 5;
    int row0 = blockIdx.x * 64;

    // load W2 (1560 uint4)
    for (int i = tid; i < 24 * 520 / 8; i += 128)
        ((uint4*)sW2)[i] = ((const uint4*)g_W2bf)[i];

    uint32_t w2base = smem_u32(sW2);
    uint32_t pbase[3] = {smem_u32(sP[0]), smem_u32(sP[1]), smem_u32(sP[2])};

    float acc[3][3][4];   // [S-matrix][ntile][frag]
#pragma unroll
    for (int i = 0; i < 3; i++)
#pragma unroll
        for (int j = 0; j < 3; j++)
#pragma unroll
            for (int k = 0; k < 4; k++) acc[i][j][k] = 0.f;

    for (int kt = 0; kt < 16; kt++) {
        int k0 = kt * 32;
        __syncthreads();   // previous iter's ldmatrix done before restage
#pragma unroll
        for (int it = 0; it < 2; it++) {
            int slot = tid + it * 128;      // 256 slots: 64 rows x 4 q
            int r = slot >> 2, q = slot & 3;
            const float* ap = inp_a + (size_t)(row0 + r) * DD + k0 + q * 8;
            float4 a0 = *(const float4*)ap;
            float4 a1 = *(const float4*)(ap + 4);
            uint4 hu = *(const uint4*)(g_hmean_bf + (size_t)(row0 + r) * DD + k0 + q * 8);
            float av[8] = {a0.x, a0.y, a0.z, a0.w, a1.x, a1.y, a1.z, a1.w};
            float hv[8];
            {
                uint32_t hw[4] = {hu.x, hu.y, hu.z, hu.w};
#pragma unroll
                for (int j = 0; j < 4; j++) {
                    float2 f = __bfloat1622float2(*(__nv_bfloat162*)&hw[j]);
                    hv[2 * j] = f.x; hv[2 * j + 1] = f.y;
                }
            }
            uint4 u1, u2, u3;
            u1.x = pack_bf2(av[0]*av[0], av[1]*av[1]);
            u1.y = pack_bf2(av[2]*av[2], av[3]*av[3]);
            u1.z = pack_bf2(av[4]*av[4], av[5]*av[5]);
            u1.w = pack_bf2(av[6]*av[6], av[7]*av[7]);
            u2.x = pack_bf2(hv[0]*hv[0], hv[1]*hv[1]);
            u2.y = pack_bf2(hv[2]*hv[2], hv[3]*hv[3]);
            u2.z = pack_bf2(hv[4]*hv[4], hv[5]*hv[5]);
            u2.w = pack_bf2(hv[6]*hv[6], hv[7]*hv[7]);
            u3.x = pack_bf2(av[0]*hv[0], av[1]*hv[1]);
            u3.y = pack_bf2(av[2]*hv[2], av[3]*hv[3]);
            u3.z = pack_bf2(av[4]*hv[4], av[5]*hv[5]);
            u3.w = pack_bf2(av[6]*hv[6], av[7]*hv[7]);
            uint32_t off = (uint32_t)(r * 64 + ((q ^ ((r >> 1) & 3)) << 4));
            *(uint4*)((char*)sP[0] + off) = u1;
            *(uint4*)((char*)sP[1] + off) = u2;
            *(uint4*)((char*)sP[2] + off) = u3;
        }
        __syncthreads();

#pragma unroll
        for (int ks = 0; ks < 2; ks++) {
            // A fragments for P1,P2,P3 (same address pattern for all three)
            int ar = w * 16 + (lane & 15);
            int aq = ks * 2 + (lane >> 4);
            uint32_t aoff = (uint32_t)(ar * 64 + ((aq ^ ((ar >> 1) & 3)) << 4));
            uint32_t f[3][4];
#pragma unroll
            for (int s = 0; s < 3; s++) {
                asm volatile("ldmatrix.sync.aligned.m8n8.x4.shared.b16 {%0,%1,%2,%3}, [%4];"
                             : "=r"(f[s][0]), "=r"(f[s][1]), "=r"(f[s][2]), "=r"(f[s][3])
                             : "r"(pbase[s] + aoff));
            }
            // B fragments from persistent W2 smem (global k index)
            uint32_t bfr[3][2];
#pragma unroll
            for (int nt = 0; nt < 3; nt++) {
                int br = nt * 8 + (lane & 7);
                int bk = k0 + (ks * 2 + ((lane >> 3) & 1)) * 8;
                uint32_t addr = w2base + (uint32_t)(br * 1040 + bk * 2);
                asm volatile("ldmatrix.sync.aligned.m8n8.x2.shared.b16 {%0,%1}, [%2];"
                             : "=r"(bfr[nt][0]), "=r"(bfr[nt][1])
                             : "r"(addr));
            }
#pragma unroll
            for (int s = 0; s < 3; s++)
#pragma unroll
                for (int nt = 0; nt < 3; nt++) {
                    asm volatile(
                        "mma.sync.aligned.m16n8k16.row.col.f32.bf16.bf16.f32 "
                        "{%0,%1,%2,%3}, {%4,%5,%6,%7}, {%8,%9}, {%0,%1,%2,%3};"
                        : "+f"(acc[s][nt][0]), "+f"(acc[s][nt][1]),
                          "+f"(acc[s][nt][2]), "+f"(acc[s][nt][3])
                        : "r"(f[s][0]), "r"(f[s][1]), "r"(f[s][2]), "r"(f[s][3]),
                          "r"(bfr[nt][0]), "r"(bfr[nt][1]));
                }
        }
    }

    // ---- epilogue: persp = S3 * rsqrt(max(S1,eps)) * rsqrt(max(S2,eps)) ----
    int rg0 = row0 + w * 16 + (lane >> 2);   // rows rg0, rg0+8
#pragma unroll
    for (int nt = 0; nt < 3; nt++) {
        int c0 = nt * 8 + (lane & 3) * 2;
#pragma unroll
        for (int half = 0; half < 2; half++) {      // frag idx 0,1 vs 2,3
            int rg = rg0 + half * 8;
            float s1a = acc[0][nt][half * 2],     s1b = acc[0][nt][half * 2 + 1];
            float s2a = acc[1][nt][half * 2],     s2b = acc[1][nt][half * 2 + 1];
            float s3a = acc[2][nt][half * 2],     s3b = acc[2][nt][half * 2 + 1];
            float va = s3a * rsqrtf(fmaxf(s1a, EPSV)) * rsqrtf(fmaxf(s2a, EPSV));
            float vb = s3b * rsqrtf(fmaxf(s1b, EPSV)) * rsqrtf(fmaxf(s2b, EPSV));
            if (c0 < PP) {
                out[(size_t)rg * PP + c0] = va;
                if (dup) out[(size_t)BB * TT * PP + (size_t)rg * PP + c0] = va;
            }
            if (c0 + 1 < PP) {
                out[(size_t)rg * PP + c0 + 1] = vb;
                if (dup) out[(size_t)BB * TT * PP + (size_t)rg * PP + c0 + 1] = vb;
            }
        }
    }
}

// ---------------------------------------------------------------------------
extern "C" void kernel_launch(void* const* d_in, const int* in_sizes, int n_in,
                              void* d_out, int out_size) {
    const float* inp_a = (const float*)d_in[0];
    const float* inp_b = (const float*)d_in[1];
    const float* W     = (const float*)d_in[2];
    float* out = (float*)d_out;
    int dup = (out_size >= 2 * BB * TT * PP) ? 1 : 0;

    void *p_nbn_bf, *p_nbnT_bf, *p_nanT_bf, *p_alphaTb, *p_colpart, *p_hmean_bf;
    cudaGetSymbolAddress(&p_nbn_bf, g_nbn_bf);
    cudaGetSymbolAddress(&p_nbnT_bf, g_nbnT_bf);
    cudaGetSymbolAddress(&p_nanT_bf, g_nanT_bf);
    cudaGetSymbolAddress(&p_alphaTb, g_alphaTb);
    cudaGetSymbolAddress(&p_colpart, g_colpart);
    cudaGetSymbolAddress(&p_hmean_bf, g_hmean_bf);

    // 1) normalize + transpose -> bf16; W^2 prepack (independent)
    k_normT<<<dim3(TT / 16, BB, 2), 256>>>(inp_a, inp_b);
    k_w2<<<(24 * 520 + 255) / 256, 256>>>(W);

    // 2) GEMM1: alphaTb[e][d] = bf16( sum_t nbnT[d,t]*nanT[e,t] ) + colpart sumsq
    k_gemm_bf16<<<dim3(4, 4, BB), 256>>>(
        (const __nv_bfloat16*)p_nbnT_bf, TT, (size_t)DD * TT,
        (const __nv_bfloat16*)p_nanT_bf, TT, (size_t)DD * TT,
        (__nv_bfloat16*)p_alphaTb, (size_t)DD * DD,
        (float*)p_colpart, TT, 1);

    // 3) GEMM2: hmean_bf[t][e] = bf16( (sum_d alphaTb[e,d]*nbn[t,d]) * invcol[e] )
    k_gemm_bf16<<<dim3(4, 2, BB), 256>>>(
        (const __nv_bfloat16*)p_alphaTb, DD, (size_t)DD * DD,
        (const __nv_bfloat16*)p_nbn_bf, DD, (size_t)TT * DD,
        (__nv_bfloat16*)p_hmean_bf, (size_t)TT * DD,
        (float*)p_colpart, DD, 2);

    // 4) perspective scores via tensor cores
    k_persp2<<<BB * TT / 64, 128>>>(inp_a, out, dup);
}

// round 15
// speedup vs baseline: 1.0155x; 1.0155x over previous
#include <cuda_runtime.h>
#include <cuda_bf16.h>
#include <cstdint>

#define BB 32
#define TT 256
#define DD 512
#define PP 20
#define EPSV 1e-12f

// ---------------- scratch (__device__ globals; no cudaMalloc allowed) ------
__device__ __align__(16) __nv_bfloat16 g_nbn_bf [BB * TT * DD];   // [b][t][d]
__device__ __align__(16) __nv_bfloat16 g_nbnT_bf[BB * DD * TT];   // [b][d][t]
__device__ __align__(16) __nv_bfloat16 g_nanT_bf[BB * DD * TT];   // [b][d][t]
__device__ __align__(16) __nv_bfloat16 g_alphaTb[(size_t)BB * DD * DD]; // [b][e][d]
__device__ __align__(16) float g_colpart[BB * 4 * DD];            // per (b, mtile, e)
__device__ __align__(16) __nv_bfloat16 g_hmean_bf[BB * TT * DD];  // [b][t][e]
__device__ __align__(16) __nv_bfloat16 g_W2bf[24 * 520];          // W^2, padded

__device__ __forceinline__ uint32_t smem_u32(const void* p) {
    return (uint32_t)__cvta_generic_to_shared(p);
}
// pack two fp32 -> bf16x2 (lo = x, hi = y), round-to-nearest-even
__device__ __forceinline__ uint32_t pack_bf2(float x, float y) {
    uint32_t r;
    asm("cvt.rn.bf16x2.f32 %0, %1, %2;" : "=r"(r) : "f"(y), "f"(x));
    return r;
}

// ---------------------------------------------------------------------------
// Kernel 1: row l2-normalize + transpose, bf16 outputs.
// ---------------------------------------------------------------------------
__global__ void __launch_bounds__(256) k_normT(const float* __restrict__ a,
                                               const float* __restrict__ b) {
    __shared__ float s[16 * 513];
    __shared__ float sinv[16];
    int which = blockIdx.z;
    int bb = blockIdx.y;
    int t0 = blockIdx.x * 16;
    const float* src = (which ? b : a) + ((size_t)bb * TT + t0) * DD;
    int tid = threadIdx.x;

#pragma unroll
    for (int i = 0; i < 8; i++) {
        int idx = tid + i * 256;
        int r = idx >> 7, c4 = idx & 127;
        float4 v = *(const float4*)(src + (size_t)r * DD + c4 * 4);
        float* sr = s + r * 513 + c4 * 4;
        sr[0] = v.x; sr[1] = v.y; sr[2] = v.z; sr[3] = v.w;
    }
    __syncthreads();

    int wid = tid >> 5, lid = tid & 31;
#pragma unroll
    for (int rr = 0; rr < 2; rr++) {
        int r = wid * 2 + rr;
        float ss = 0.f;
#pragma unroll
        for (int j = 0; j < 16; j++) { float v = s[r * 513 + lid + 32 * j]; ss += v * v; }
#pragma unroll
        for (int o = 16; o > 0; o >>= 1) ss += __shfl_xor_sync(0xffffffffu, ss, o);
        if (lid == 0) sinv[r] = rsqrtf(fmaxf(ss, EPSV));
    }
    __syncthreads();

    __nv_bfloat16* dstT = (which ? g_nbnT_bf : g_nanT_bf) + (size_t)bb * DD * TT;
#pragma unroll
    for (int i = 0; i < 8; i++) {
        int idx = tid + i * 256;
        int d = idx >> 2, jq = (idx & 3) * 4;
        float o0 = s[(jq + 0) * 513 + d] * sinv[jq + 0];
        float o1 = s[(jq + 1) * 513 + d] * sinv[jq + 1];
        float o2 = s[(jq + 2) * 513 + d] * sinv[jq + 2];
        float o3 = s[(jq + 3) * 513 + d] * sinv[jq + 3];
        uint2 u = make_uint2(pack_bf2(o0, o1), pack_bf2(o2, o3));
        *(uint2*)(dstT + (size_t)d * TT + t0 + jq) = u;
    }
    if (which) {
        __nv_bfloat16* dst = g_nbn_bf + ((size_t)bb * TT + t0) * DD;
#pragma unroll
        for (int i = 0; i < 8; i++) {
            int idx = tid + i * 256;
            int r = idx >> 7, c4 = idx & 127;
            float inv = sinv[r];
            float* sr = s + r * 513 + c4 * 4;
            uint2 u = make_uint2(pack_bf2(sr[0] * inv, sr[1] * inv),
                                 pack_bf2(sr[2] * inv, sr[3] * inv));
            *(uint2*)(dst + (size_t)r * DD + c4 * 4) = u;
        }
    }
}

// ---------------------------------------------------------------------------
// bf16 mma.sync GEMM, 4-stage cp.async pipeline, one barrier per K-chunk.
// CTA tile 128x128, K-chunk 32. Store transposed: C[n*512 + m], bf16.
// mode 1 (GEMM1): also emit per-CTA column sum-of-squares partials
// mode 2 (GEMM2): scale output by rsqrt(max(sum_j colpart[j][m], eps))
// ---------------------------------------------------------------------------
__global__ void __launch_bounds__(256, 2) k_gemm_bf16(
    const __nv_bfloat16* __restrict__ Ag, int lda, size_t strideA,
    const __nv_bfloat16* __restrict__ Bg, int ldb, size_t strideB,
    __nv_bfloat16* __restrict__ Cg, size_t strideC,
    float* __restrict__ colpart, int Ktot, int mode) {
    __shared__ __align__(16) char sm[4 * 16384];  // 64KB

    int b = blockIdx.z;
    int m0 = blockIdx.x * 128, n0 = blockIdx.y * 128;
    const __nv_bfloat16* A  = Ag + (size_t)b * strideA + (size_t)m0 * lda;
    const __nv_bfloat16* Bp = Bg + (size_t)b * strideB + (size_t)n0 * ldb;

    int tid = threadIdx.x, lane = tid & 31, wid = tid >> 5;
    int wm = wid & 1, wn = wid >> 1;
    uint32_t smbase = smem_u32(sm);

    float acc[4][4][4];
#pragma unroll
    for (int i = 0; i < 4; i++)
#pragma unroll
        for (int j = 0; j < 4; j++)
#pragma unroll
            for (int k = 0; k < 4; k++) acc[i][j][k] = 0.f;

    int nkt = Ktot / 32;

    auto issue_chunk = [&](int kt) {
        uint32_t base = smbase + (uint32_t)(kt & 3) * 16384u;
        int k0 = kt * 32;
#pragma unroll
        for (int i = 0; i < 2; i++) {
            int idx = tid + i * 256;
            int r = idx >> 2, q = idx & 3;
            uint32_t off = (uint32_t)(r * 64 + ((q ^ ((r >> 1) & 3)) << 4));
            const __nv_bfloat16* srcA = A + (size_t)r * lda + k0 + q * 8;
            asm volatile("cp.async.cg.shared.global [%0], [%1], 16;"
                         :: "r"(base + off), "l"(srcA));
            const __nv_bfloat16* srcB = Bp + (size_t)r * ldb + k0 + q * 8;
            asm volatile("cp.async.cg.shared.global [%0], [%1], 16;"
                         :: "r"(base + 8192u + off), "l"(srcB));
        }
        asm volatile("cp.async.commit_group;");
    };

    issue_chunk(0);
    issue_chunk(1);
    issue_chunk(2);

    for (int kt = 0; kt < nkt; kt++) {
        asm volatile("cp.async.wait_group 2;" ::: "memory");
        __syncthreads();
        if (kt + 3 < nkt) issue_chunk(kt + 3);

        uint32_t baseA = smbase + (uint32_t)(kt & 3) * 16384u;
        uint32_t baseB = baseA + 8192u;

#pragma unroll
        for (int ks = 0; ks < 2; ks++) {
            uint32_t af[4][4], bf[4][2];
#pragma unroll
            for (int mt = 0; mt < 4; mt++) {
                int r = wm * 64 + mt * 16 + (lane & 15);
                int q = ks * 2 + (lane >> 4);
                uint32_t addr = baseA + (uint32_t)(r * 64 + ((q ^ ((r >> 1) & 3)) << 4));
                asm volatile("ldmatrix.sync.aligned.m8n8.x4.shared.b16 {%0,%1,%2,%3}, [%4];"
                             : "=r"(af[mt][0]), "=r"(af[mt][1]),
                               "=r"(af[mt][2]), "=r"(af[mt][3])
                             : "r"(addr));
            }
#pragma unroll
            for (int nt = 0; nt < 4; nt++) {
                int r = wn * 32 + nt * 8 + (lane & 7);
                int q = ks * 2 + ((lane >> 3) & 1);
                uint32_t addr = baseB + (uint32_t)(r * 64 + ((q ^ ((r >> 1) & 3)) << 4));
                asm volatile("ldmatrix.sync.aligned.m8n8.x2.shared.b16 {%0,%1}, [%2];"
                             : "=r"(bf[nt][0]), "=r"(bf[nt][1])
                             : "r"(addr));
            }
#pragma unroll
            for (int mt = 0; mt < 4; mt++)
#pragma unroll
                for (int nt = 0; nt < 4; nt++) {
                    asm volatile(
                        "mma.sync.aligned.m16n8k16.row.col.f32.bf16.bf16.f32 "
                        "{%0,%1,%2,%3}, {%4,%5,%6,%7}, {%8,%9}, {%0,%1,%2,%3};"
                        : "+f"(acc[mt][nt][0]), "+f"(acc[mt][nt][1]),
                          "+f"(acc[mt][nt][2]), "+f"(acc[mt][nt][3])
                        : "r"(af[mt][0]), "r"(af[mt][1]),
                          "r"(af[mt][2]), "r"(af[mt][3]),
                          "r"(bf[nt][0]), "r"(bf[nt][1]));
                }
        }
    }

    // ---- epilogue ----
    __nv_bfloat16* Cb = Cg + (size_t)b * strideC;

    if (mode == 1) {
#pragma unroll
        for (int mt = 0; mt < 4; mt++) {
            int r0 = m0 + wm * 64 + mt * 16 + (lane >> 2);
#pragma unroll
            for (int nt = 0; nt < 4; nt++) {
                int c0 = n0 + wn * 32 + nt * 8 + (lane & 3) * 2;
                Cb[(size_t)c0 * 512 + r0]           = __float2bfloat16(acc[mt][nt][0]);
                Cb[(size_t)(c0 + 1) * 512 + r0]     = __float2bfloat16(acc[mt][nt][1]);
                Cb[(size_t)c0 * 512 + r0 + 8]       = __float2bfloat16(acc[mt][nt][2]);
                Cb[(size_t)(c0 + 1) * 512 + r0 + 8] = __float2bfloat16(acc[mt][nt][3]);
            }
        }
        float p0[4], p1[4];
#pragma unroll
        for (int nt = 0; nt < 4; nt++) {
            float s0 = 0.f, s1 = 0.f;
#pragma unroll
            for (int mt = 0; mt < 4; mt++) {
                s0 += acc[mt][nt][0] * acc[mt][nt][0] + acc[mt][nt][2] * acc[mt][nt][2];
                s1 += acc[mt][nt][1] * acc[mt][nt][1] + acc[mt][nt][3] * acc[mt][nt][3];
            }
#pragma unroll
            for (int o = 4; o < 32; o <<= 1) {
                s0 += __shfl_xor_sync(0xffffffffu, s0, o);
                s1 += __shfl_xor_sync(0xffffffffu, s1, o);
            }
            p0[nt] = s0; p1[nt] = s1;
        }
        __syncthreads();
        float* psum = (float*)sm;
        if (wm == 0 && lane < 4) {
#pragma unroll
            for (int nt = 0; nt < 4; nt++) {
                int idx = wn * 32 + nt * 8 + lane * 2;
                psum[idx] = p0[nt]; psum[idx + 1] = p1[nt];
            }
        }
        __syncthreads();
        if (wm == 1 && lane < 4) {
#pragma unroll
            for (int nt = 0; nt < 4; nt++) {
                int idx = wn * 32 + nt * 8 + lane * 2;
                psum[idx] += p0[nt]; psum[idx + 1] += p1[nt];
            }
        }
        __syncthreads();
        if (tid < 128)
            colpart[((size_t)b * 4 + blockIdx.x) * DD + n0 + tid] = psum[tid];
    } else {
        const float* cp = colpart + (size_t)b * 4 * DD;
#pragma unroll
        for (int mt = 0; mt < 4; mt++) {
            int r0 = m0 + wm * 64 + mt * 16 + (lane >> 2);
            float cs0 = cp[r0] + cp[DD + r0] + cp[2 * DD + r0] + cp[3 * DD + r0];
            float cs1 = cp[r0 + 8] + cp[DD + r0 + 8] + cp[2 * DD + r0 + 8] + cp[3 * DD + r0 + 8];
            float sc0 = rsqrtf(fmaxf(cs0, EPSV));
            float sc1 = rsqrtf(fmaxf(cs1, EPSV));
#pragma unroll
            for (int nt = 0; nt < 4; nt++) {
                int c0 = n0 + wn * 32 + nt * 8 + (lane & 3) * 2;
                Cb[(size_t)c0 * 512 + r0]           = __float2bfloat16(acc[mt][nt][0] * sc0);
                Cb[(size_t)(c0 + 1) * 512 + r0]     = __float2bfloat16(acc[mt][nt][1] * sc0);
                Cb[(size_t)c0 * 512 + r0 + 8]       = __float2bfloat16(acc[mt][nt][2] * sc1);
                Cb[(size_t)(c0 + 1) * 512 + r0 + 8] = __float2bfloat16(acc[mt][nt][3] * sc1);
            }
        }
    }
}

// ---------------------------------------------------------------------------
// W^2 prepack: g_W2bf[24][520] bf16, zero-padded beyond (20, 512).
// ---------------------------------------------------------------------------
__global__ void k_w2(const float* __restrict__ W) {
    int i = blockIdx.x * blockDim.x + threadIdx.x;
    if (i >= 24 * 520) return;
    int p = i / 520, d = i - p * 520;
    float v = 0.f;
    if (p < PP && d < DD) { float w = W[p * DD + d]; v = w * w; }
    g_W2bf[i] = __float2bfloat16(v);
}

// ---------------------------------------------------------------------------
// Perspective via tensor cores, A-fragments built DIRECTLY in registers.
// mma.m16n8k16 A layout: thread(lane) owns {r,c},{r+8,c},{r,c+8},{r+8,c+8}
// with r=lane>>2, c=(lane&3)*2 (pairs c,c+1). Each thread LDGs its own
// a (2 fp32) and h (2 bf16) pairs, computes P1=a*a,P2=h*h,P3=a*h in fp32,
// packs to bf16 fragments. No smem staging, no per-chunk syncs.
// W2 B-fragments via persistent smem + ldmatrix (validated in R14).
// ---------------------------------------------------------------------------
__global__ void __launch_bounds__(128) k_persp2(const float* __restrict__ inp_a,
                                                float* __restrict__ out, int dup) {
    __shared__ __align__(16) __nv_bfloat16 sW2[24 * 520];   // 24.4KB, rows 1040B

    int tid = threadIdx.x, lane = tid & 31, w = tid >> 5;
    int row0 = blockIdx.x * 64;

    for (int i = tid; i < 24 * 520 / 8; i += 128)
        ((uint4*)sW2)[i] = ((const uint4*)g_W2bf)[i];
    __syncthreads();
    uint32_t w2base = smem_u32(sW2);

    int r = lane >> 2, c = (lane & 3) * 2;
    int R = row0 + w * 16 + r;                 // rows R, R+8
    const float* a0p = inp_a + (size_t)R * DD;
    const float* a1p = inp_a + (size_t)(R + 8) * DD;
    const __nv_bfloat16* h0p = g_hmean_bf + (size_t)R * DD;
    const __nv_bfloat16* h1p = g_hmean_bf + (size_t)(R + 8) * DD;

    float acc[3][3][4];   // [S-matrix][ntile][frag]
#pragma unroll
    for (int i = 0; i < 3; i++)
#pragma unroll
        for (int j = 0; j < 3; j++)
#pragma unroll
            for (int k = 0; k < 4; k++) acc[i][j][k] = 0.f;

#pragma unroll 4
    for (int kt = 0; kt < 32; kt++) {          // K-steps of 16
        int k0 = kt * 16;
        // loads: a pairs (fp32x2) and h pairs (bf16x2) at the 4 fragment spots
        float2 aA = *(const float2*)(a0p + k0 + c);
        float2 aB = *(const float2*)(a1p + k0 + c);
        float2 aC = *(const float2*)(a0p + k0 + c + 8);
        float2 aD = *(const float2*)(a1p + k0 + c + 8);
        uint32_t hAu = *(const uint32_t*)(h0p + k0 + c);
        uint32_t hBu = *(const uint32_t*)(h1p + k0 + c);
        uint32_t hCu = *(const uint32_t*)(h0p + k0 + c + 8);
        uint32_t hDu = *(const uint32_t*)(h1p + k0 + c + 8);
        float2 hA = __bfloat1622float2(*(__nv_bfloat162*)&hAu);
        float2 hB = __bfloat1622float2(*(__nv_bfloat162*)&hBu);
        float2 hC = __bfloat1622float2(*(__nv_bfloat162*)&hCu);
        float2 hD = __bfloat1622float2(*(__nv_bfloat162*)&hDu);

        uint32_t f[3][4];
        f[0][0] = pack_bf2(aA.x * aA.x, aA.y * aA.y);
        f[0][1] = pack_bf2(aB.x * aB.x, aB.y * aB.y);
        f[0][2] = pack_bf2(aC.x * aC.x, aC.y * aC.y);
        f[0][3] = pack_bf2(aD.x * aD.x, aD.y * aD.y);
        f[1][0] = pack_bf2(hA.x * hA.x, hA.y * hA.y);
        f[1][1] = pack_bf2(hB.x * hB.x, hB.y * hB.y);
        f[1][2] = pack_bf2(hC.x * hC.x, hC.y * hC.y);
        f[1][3] = pack_bf2(hD.x * hD.x, hD.y * hD.y);
        f[2][0] = pack_bf2(aA.x * hA.x, aA.y * hA.y);
        f[2][1] = pack_bf2(aB.x * hB.x, aB.y * hB.y);
        f[2][2] = pack_bf2(aC.x * hC.x, aC.y * hC.y);
        f[2][3] = pack_bf2(aD.x * hD.x, aD.y * hD.y);

        // W2 B-fragments (persistent smem)
        uint32_t bfr[3][2];
#pragma unroll
        for (int nt = 0; nt < 3; nt++) {
            int br = nt * 8 + (lane & 7);
            int bk = k0 + ((lane >> 3) & 1) * 8;
            uint32_t addr = w2base + (uint32_t)(br * 1040 + bk * 2);
            asm volatile("ldmatrix.sync.aligned.m8n8.x2.shared.b16 {%0,%1}, [%2];"
                         : "=r"(bfr[nt][0]), "=r"(bfr[nt][1])
                         : "r"(addr));
        }
#pragma unroll
        for (int s = 0; s < 3; s++)
#pragma unroll
            for (int nt = 0; nt < 3; nt++) {
                asm volatile(
                    "mma.sync.aligned.m16n8k16.row.col.f32.bf16.bf16.f32 "
                    "{%0,%1,%2,%3}, {%4,%5,%6,%7}, {%8,%9}, {%0,%1,%2,%3};"
                    : "+f"(acc[s][nt][0]), "+f"(acc[s][nt][1]),
                      "+f"(acc[s][nt][2]), "+f"(acc[s][nt][3])
                    : "r"(f[s][0]), "r"(f[s][1]), "r"(f[s][2]), "r"(f[s][3]),
                      "r"(bfr[nt][0]), "r"(bfr[nt][1]));
            }
    }

    // ---- epilogue: persp = S3 * rsqrt(max(S1,eps)) * rsqrt(max(S2,eps)) ----
    int rg0 = row0 + w * 16 + (lane >> 2);   // rows rg0, rg0+8
#pragma unroll
    for (int nt = 0; nt < 3; nt++) {
        int c0 = nt * 8 + (lane & 3) * 2;
#pragma unroll
        for (int half = 0; half < 2; half++) {
            int rg = rg0 + half * 8;
            float s1a = acc[0][nt][half * 2],     s1b = acc[0][nt][half * 2 + 1];
            float s2a = acc[1][nt][half * 2],     s2b = acc[1][nt][half * 2 + 1];
            float s3a = acc[2][nt][half * 2],     s3b = acc[2][nt][half * 2 + 1];
            float va = s3a * rsqrtf(fmaxf(s1a, EPSV)) * rsqrtf(fmaxf(s2a, EPSV));
            float vb = s3b * rsqrtf(fmaxf(s1b, EPSV)) * rsqrtf(fmaxf(s2b, EPSV));
            if (c0 < PP) {
                out[(size_t)rg * PP + c0] = va;
                if (dup) out[(size_t)BB * TT * PP + (size_t)rg * PP + c0] = va;
            }
            if (c0 + 1 < PP) {
                out[(size_t)rg * PP + c0 + 1] = vb;
                if (dup) out[(size_t)BB * TT * PP + (size_t)rg * PP + c0 + 1] = vb;
            }
        }
    }
}

// ---------------------------------------------------------------------------
extern "C" void kernel_launch(void* const* d_in, const int* in_sizes, int n_in,
                              void* d_out, int out_size) {
    const float* inp_a = (const float*)d_in[0];
    const float* inp_b = (const float*)d_in[1];
    const float* W     = (const float*)d_in[2];
    float* out = (float*)d_out;
    int dup = (out_size >= 2 * BB * TT * PP) ? 1 : 0;

    void *p_nbn_bf, *p_nbnT_bf, *p_nanT_bf, *p_alphaTb, *p_colpart, *p_hmean_bf;
    cudaGetSymbolAddress(&p_nbn_bf, g_nbn_bf);
    cudaGetSymbolAddress(&p_nbnT_bf, g_nbnT_bf);
    cudaGetSymbolAddress(&p_nanT_bf, g_nanT_bf);
    cudaGetSymbolAddress(&p_alphaTb, g_alphaTb);
    cudaGetSymbolAddress(&p_colpart, g_colpart);
    cudaGetSymbolAddress(&p_hmean_bf, g_hmean_bf);

    // 1) normalize + transpose -> bf16; W^2 prepack (independent)
    k_normT<<<dim3(TT / 16, BB, 2), 256>>>(inp_a, inp_b);
    k_w2<<<(24 * 520 + 255) / 256, 256>>>(W);

    // 2) GEMM1: alphaTb[e][d] = bf16( sum_t nbnT[d,t]*nanT[e,t] ) + colpart sumsq
    k_gemm_bf16<<<dim3(4, 4, BB), 256>>>(
        (const __nv_bfloat16*)p_nbnT_bf, TT, (size_t)DD * TT,
        (const __nv_bfloat16*)p_nanT_bf, TT, (size_t)DD * TT,
        (__nv_bfloat16*)p_alphaTb, (size_t)DD * DD,
        (float*)p_colpart, TT, 1);

    // 3) GEMM2: hmean_bf[t][e] = bf16( (sum_d alphaTb[e,d]*nbn[t,d]) * invcol[e] )
    k_gemm_bf16<<<dim3(4, 2, BB), 256>>>(
        (const __nv_bfloat16*)p_alphaTb, DD, (size_t)DD * DD,
        (const __nv_bfloat16*)p_nbn_bf, DD, (size_t)TT * DD,
        (__nv_bfloat16*)p_hmean_bf, (size_t)TT * DD,
        (float*)p_colpart, DD, 2);

    // 4) perspective scores via tensor cores (register-direct A fragments)
    k_persp2<<<BB * TT / 64, 128>>>(inp_a, out, dup);
}

// round 16
// speedup vs baseline: 1.1606x; 1.1429x over previous
#include <cuda_runtime.h>
#include <cuda_bf16.h>
#include <cstdint>

#define BB 32
#define TT 256
#define DD 512
#define PP 20
#define EPSV 1e-12f

// ---------------- scratch (__device__ globals; no cudaMalloc allowed) ------
__device__ __align__(16) __nv_bfloat16 g_nbn_bf [BB * TT * DD];   // [b][t][d]
__device__ __align__(16) __nv_bfloat16 g_nbnT_bf[BB * DD * TT];   // [b][d][t]
__device__ __align__(16) __nv_bfloat16 g_nanT_bf[BB * DD * TT];   // [b][d][t]
__device__ __align__(16) __nv_bfloat16 g_alphaTb[(size_t)BB * DD * DD]; // [b][e][d]
__device__ __align__(16) float g_colpart[BB * 4 * DD];            // per (b, mtile, e)
__device__ __align__(16) __nv_bfloat16 g_hmean_bf[BB * TT * DD];  // [b][t][e]

__device__ __forceinline__ uint32_t smem_u32(const void* p) {
    return (uint32_t)__cvta_generic_to_shared(p);
}
// pack two fp32 -> bf16x2 (lo = x, hi = y), round-to-nearest-even
__device__ __forceinline__ uint32_t pack_bf2(float x, float y) {
    uint32_t r;
    asm("cvt.rn.bf16x2.f32 %0, %1, %2;" : "=r"(r) : "f"(y), "f"(x));
    return r;
}

// ---------------------------------------------------------------------------
// Kernel 1: row l2-normalize + transpose, bf16 outputs.
// ---------------------------------------------------------------------------
__global__ void __launch_bounds__(256) k_normT(const float* __restrict__ a,
                                               const float* __restrict__ b) {
    __shared__ float s[16 * 513];
    __shared__ float sinv[16];
    int which = blockIdx.z;
    int bb = blockIdx.y;
    int t0 = blockIdx.x * 16;
    const float* src = (which ? b : a) + ((size_t)bb * TT + t0) * DD;
    int tid = threadIdx.x;

#pragma unroll
    for (int i = 0; i < 8; i++) {
        int idx = tid + i * 256;
        int r = idx >> 7, c4 = idx & 127;
        float4 v = *(const float4*)(src + (size_t)r * DD + c4 * 4);
        float* sr = s + r * 513 + c4 * 4;
        sr[0] = v.x; sr[1] = v.y; sr[2] = v.z; sr[3] = v.w;
    }
    __syncthreads();

    int wid = tid >> 5, lid = tid & 31;
#pragma unroll
    for (int rr = 0; rr < 2; rr++) {
        int r = wid * 2 + rr;
        float ss = 0.f;
#pragma unroll
        for (int j = 0; j < 16; j++) { float v = s[r * 513 + lid + 32 * j]; ss += v * v; }
#pragma unroll
        for (int o = 16; o > 0; o >>= 1) ss += __shfl_xor_sync(0xffffffffu, ss, o);
        if (lid == 0) sinv[r] = rsqrtf(fmaxf(ss, EPSV));
    }
    __syncthreads();

    __nv_bfloat16* dstT = (which ? g_nbnT_bf : g_nanT_bf) + (size_t)bb * DD * TT;
#pragma unroll
    for (int i = 0; i < 8; i++) {
        int idx = tid + i * 256;
        int d = idx >> 2, jq = (idx & 3) * 4;
        float o0 = s[(jq + 0) * 513 + d] * sinv[jq + 0];
        float o1 = s[(jq + 1) * 513 + d] * sinv[jq + 1];
        float o2 = s[(jq + 2) * 513 + d] * sinv[jq + 2];
        float o3 = s[(jq + 3) * 513 + d] * sinv[jq + 3];
        uint2 u = make_uint2(pack_bf2(o0, o1), pack_bf2(o2, o3));
        *(uint2*)(dstT + (size_t)d * TT + t0 + jq) = u;
    }
    if (which) {
        __nv_bfloat16* dst = g_nbn_bf + ((size_t)bb * TT + t0) * DD;
#pragma unroll
        for (int i = 0; i < 8; i++) {
            int idx = tid + i * 256;
            int r = idx >> 7, c4 = idx & 127;
            float inv = sinv[r];
            float* sr = s + r * 513 + c4 * 4;
            uint2 u = make_uint2(pack_bf2(sr[0] * inv, sr[1] * inv),
                                 pack_bf2(sr[2] * inv, sr[3] * inv));
            *(uint2*)(dst + (size_t)r * DD + c4 * 4) = u;
        }
    }
}

// ---------------------------------------------------------------------------
// bf16 mma.sync GEMM, 4-stage cp.async pipeline, one barrier per K-chunk.
// CTA tile 128x128, K-chunk 32. Store transposed: C[n*512 + m], bf16.
// mode 1 (GEMM1): also emit per-CTA column sum-of-squares partials
// mode 2 (GEMM2): scale output by rsqrt(max(sum_j colpart[j][m], eps))
// ---------------------------------------------------------------------------
__global__ void __launch_bounds__(256, 2) k_gemm_bf16(
    const __nv_bfloat16* __restrict__ Ag, int lda, size_t strideA,
    const __nv_bfloat16* __restrict__ Bg, int ldb, size_t strideB,
    __nv_bfloat16* __restrict__ Cg, size_t strideC,
    float* __restrict__ colpart, int Ktot, int mode) {
    __shared__ __align__(16) char sm[4 * 16384];  // 64KB

    int b = blockIdx.z;
    int m0 = blockIdx.x * 128, n0 = blockIdx.y * 128;
    const __nv_bfloat16* A  = Ag + (size_t)b * strideA + (size_t)m0 * lda;
    const __nv_bfloat16* Bp = Bg + (size_t)b * strideB + (size_t)n0 * ldb;

    int tid = threadIdx.x, lane = tid & 31, wid = tid >> 5;
    int wm = wid & 1, wn = wid >> 1;
    uint32_t smbase = smem_u32(sm);

    float acc[4][4][4];
#pragma unroll
    for (int i = 0; i < 4; i++)
#pragma unroll
        for (int j = 0; j < 4; j++)
#pragma unroll
            for (int k = 0; k < 4; k++) acc[i][j][k] = 0.f;

    int nkt = Ktot / 32;

    auto issue_chunk = [&](int kt) {
        uint32_t base = smbase + (uint32_t)(kt & 3) * 16384u;
        int k0 = kt * 32;
#pragma unroll
        for (int i = 0; i < 2; i++) {
            int idx = tid + i * 256;
            int r = idx >> 2, q = idx & 3;
            uint32_t off = (uint32_t)(r * 64 + ((q ^ ((r >> 1) & 3)) << 4));
            const __nv_bfloat16* srcA = A + (size_t)r * lda + k0 + q * 8;
            asm volatile("cp.async.cg.shared.global [%0], [%1], 16;"
                         :: "r"(base + off), "l"(srcA));
            const __nv_bfloat16* srcB = Bp + (size_t)r * ldb + k0 + q * 8;
            asm volatile("cp.async.cg.shared.global [%0], [%1], 16;"
                         :: "r"(base + 8192u + off), "l"(srcB));
        }
        asm volatile("cp.async.commit_group;");
    };

    issue_chunk(0);
    issue_chunk(1);
    issue_chunk(2);

    for (int kt = 0; kt < nkt; kt++) {
        asm volatile("cp.async.wait_group 2;" ::: "memory");
        __syncthreads();
        if (kt + 3 < nkt) issue_chunk(kt + 3);

        uint32_t baseA = smbase + (uint32_t)(kt & 3) * 16384u;
        uint32_t baseB = baseA + 8192u;

#pragma unroll
        for (int ks = 0; ks < 2; ks++) {
            uint32_t af[4][4], bf[4][2];
#pragma unroll
            for (int mt = 0; mt < 4; mt++) {
                int r = wm * 64 + mt * 16 + (lane & 15);
                int q = ks * 2 + (lane >> 4);
                uint32_t addr = baseA + (uint32_t)(r * 64 + ((q ^ ((r >> 1) & 3)) << 4));
                asm volatile("ldmatrix.sync.aligned.m8n8.x4.shared.b16 {%0,%1,%2,%3}, [%4];"
                             : "=r"(af[mt][0]), "=r"(af[mt][1]),
                               "=r"(af[mt][2]), "=r"(af[mt][3])
                             : "r"(addr));
            }
#pragma unroll
            for (int nt = 0; nt < 4; nt++) {
                int r = wn * 32 + nt * 8 + (lane & 7);
                int q = ks * 2 + ((lane >> 3) & 1);
                uint32_t addr = baseB + (uint32_t)(r * 64 + ((q ^ ((r >> 1) & 3)) << 4));
                asm volatile("ldmatrix.sync.aligned.m8n8.x2.shared.b16 {%0,%1}, [%2];"
                             : "=r"(bf[nt][0]), "=r"(bf[nt][1])
                             : "r"(addr));
            }
#pragma unroll
            for (int mt = 0; mt < 4; mt++)
#pragma unroll
                for (int nt = 0; nt < 4; nt++) {
                    asm volatile(
                        "mma.sync.aligned.m16n8k16.row.col.f32.bf16.bf16.f32 "
                        "{%0,%1,%2,%3}, {%4,%5,%6,%7}, {%8,%9}, {%0,%1,%2,%3};"
                        : "+f"(acc[mt][nt][0]), "+f"(acc[mt][nt][1]),
                          "+f"(acc[mt][nt][2]), "+f"(acc[mt][nt][3])
                        : "r"(af[mt][0]), "r"(af[mt][1]),
                          "r"(af[mt][2]), "r"(af[mt][3]),
                          "r"(bf[nt][0]), "r"(bf[nt][1]));
                }
        }
    }

    // ---- epilogue ----
    __nv_bfloat16* Cb = Cg + (size_t)b * strideC;

    if (mode == 1) {
#pragma unroll
        for (int mt = 0; mt < 4; mt++) {
            int r0 = m0 + wm * 64 + mt * 16 + (lane >> 2);
#pragma unroll
            for (int nt = 0; nt < 4; nt++) {
                int c0 = n0 + wn * 32 + nt * 8 + (lane & 3) * 2;
                Cb[(size_t)c0 * 512 + r0]           = __float2bfloat16(acc[mt][nt][0]);
                Cb[(size_t)(c0 + 1) * 512 + r0]     = __float2bfloat16(acc[mt][nt][1]);
                Cb[(size_t)c0 * 512 + r0 + 8]       = __float2bfloat16(acc[mt][nt][2]);
                Cb[(size_t)(c0 + 1) * 512 + r0 + 8] = __float2bfloat16(acc[mt][nt][3]);
            }
        }
        float p0[4], p1[4];
#pragma unroll
        for (int nt = 0; nt < 4; nt++) {
            float s0 = 0.f, s1 = 0.f;
#pragma unroll
            for (int mt = 0; mt < 4; mt++) {
                s0 += acc[mt][nt][0] * acc[mt][nt][0] + acc[mt][nt][2] * acc[mt][nt][2];
                s1 += acc[mt][nt][1] * acc[mt][nt][1] + acc[mt][nt][3] * acc[mt][nt][3];
            }
#pragma unroll
            for (int o = 4; o < 32; o <<= 1) {
                s0 += __shfl_xor_sync(0xffffffffu, s0, o);
                s1 += __shfl_xor_sync(0xffffffffu, s1, o);
            }
            p0[nt] = s0; p1[nt] = s1;
        }
        __syncthreads();
        float* psum = (float*)sm;
        if (wm == 0 && lane < 4) {
#pragma unroll
            for (int nt = 0; nt < 4; nt++) {
                int idx = wn * 32 + nt * 8 + lane * 2;
                psum[idx] = p0[nt]; psum[idx + 1] = p1[nt];
            }
        }
        __syncthreads();
        if (wm == 1 && lane < 4) {
#pragma unroll
            for (int nt = 0; nt < 4; nt++) {
                int idx = wn * 32 + nt * 8 + lane * 2;
                psum[idx] += p0[nt]; psum[idx + 1] += p1[nt];
            }
        }
        __syncthreads();
        if (tid < 128)
            colpart[((size_t)b * 4 + blockIdx.x) * DD + n0 + tid] = psum[tid];
    } else {
        const float* cp = colpart + (size_t)b * 4 * DD;
#pragma unroll
        for (int mt = 0; mt < 4; mt++) {
            int r0 = m0 + wm * 64 + mt * 16 + (lane >> 2);
            float cs0 = cp[r0] + cp[DD + r0] + cp[2 * DD + r0] + cp[3 * DD + r0];
            float cs1 = cp[r0 + 8] + cp[DD + r0 + 8] + cp[2 * DD + r0 + 8] + cp[3 * DD + r0 + 8];
            float sc0 = rsqrtf(fmaxf(cs0, EPSV));
            float sc1 = rsqrtf(fmaxf(cs1, EPSV));
#pragma unroll
            for (int nt = 0; nt < 4; nt++) {
                int c0 = n0 + wn * 32 + nt * 8 + (lane & 3) * 2;
                Cb[(size_t)c0 * 512 + r0]           = __float2bfloat16(acc[mt][nt][0] * sc0);
                Cb[(size_t)(c0 + 1) * 512 + r0]     = __float2bfloat16(acc[mt][nt][1] * sc0);
                Cb[(size_t)c0 * 512 + r0 + 8]       = __float2bfloat16(acc[mt][nt][2] * sc1);
                Cb[(size_t)(c0 + 1) * 512 + r0 + 8] = __float2bfloat16(acc[mt][nt][3] * sc1);
            }
        }
    }
}

// ---------------------------------------------------------------------------
// Perspective via tensor cores, register-direct A fragments, K-split x2.
// 256 thr / 8 warps per block, 64 rows. warp = (wr = w&3 row-group) x
// (wk = w>>2 K-half). Each warp accumulates its K=256 half; wk=1 dumps
// partials to smem, wk=0 adds and writes output. W^2 squared into smem
// from W directly (k_w2 kernel eliminated).
// ---------------------------------------------------------------------------
__global__ void __launch_bounds__(256) k_persp3(const float* __restrict__ inp_a,
                                                const float* __restrict__ W,
                                                float* __restrict__ out, int dup) {
    __shared__ __align__(16) __nv_bfloat16 sW2[24 * 520];   // 24.4KB
    __shared__ __align__(16) float sred[128 * 36];          // 18.4KB

    int tid = threadIdx.x, lane = tid & 31, w = tid >> 5;
    int wr = w & 3, wk = w >> 2;
    int row0 = blockIdx.x * 64;

    // W^2 -> smem (zero-padded to 24 x 520)
    for (int i = tid; i < 24 * 520; i += 256) {
        int p = i / 520, d = i - p * 520;
        float v = 0.f;
        if (p < PP && d < DD) { float ww = W[p * DD + d]; v = ww * ww; }
        sW2[i] = __float2bfloat16(v);
    }
    __syncthreads();
    uint32_t w2base = smem_u32(sW2);

    int r = lane >> 2, c = (lane & 3) * 2;
    int R = row0 + wr * 16 + r;                // rows R, R+8
    const float* a0p = inp_a + (size_t)R * DD;
    const float* a1p = inp_a + (size_t)(R + 8) * DD;
    const __nv_bfloat16* h0p = g_hmean_bf + (size_t)R * DD;
    const __nv_bfloat16* h1p = g_hmean_bf + (size_t)(R + 8) * DD;

    float acc[3][3][4];
#pragma unroll
    for (int i = 0; i < 3; i++)
#pragma unroll
        for (int j = 0; j < 3; j++)
#pragma unroll
            for (int k = 0; k < 4; k++) acc[i][j][k] = 0.f;

    int kbase = wk * 256;
#pragma unroll 4
    for (int kt = 0; kt < 16; kt++) {          // K-steps of 16 within half
        int k0 = kbase + kt * 16;
        float2 aA = *(const float2*)(a0p + k0 + c);
        float2 aB = *(const float2*)(a1p + k0 + c);
        float2 aC = *(const float2*)(a0p + k0 + c + 8);
        float2 aD = *(const float2*)(a1p + k0 + c + 8);
        uint32_t hAu = *(const uint32_t*)(h0p + k0 + c);
        uint32_t hBu = *(const uint32_t*)(h1p + k0 + c);
        uint32_t hCu = *(const uint32_t*)(h0p + k0 + c + 8);
        uint32_t hDu = *(const uint32_t*)(h1p + k0 + c + 8);
        float2 hA = __bfloat1622float2(*(__nv_bfloat162*)&hAu);
        float2 hB = __bfloat1622float2(*(__nv_bfloat162*)&hBu);
        float2 hC = __bfloat1622float2(*(__nv_bfloat162*)&hCu);
        float2 hD = __bfloat1622float2(*(__nv_bfloat162*)&hDu);

        uint32_t f[3][4];
        f[0][0] = pack_bf2(aA.x * aA.x, aA.y * aA.y);
        f[0][1] = pack_bf2(aB.x * aB.x, aB.y * aB.y);
        f[0][2] = pack_bf2(aC.x * aC.x, aC.y * aC.y);
        f[0][3] = pack_bf2(aD.x * aD.x, aD.y * aD.y);
        f[1][0] = pack_bf2(hA.x * hA.x, hA.y * hA.y);
        f[1][1] = pack_bf2(hB.x * hB.x, hB.y * hB.y);
        f[1][2] = pack_bf2(hC.x * hC.x, hC.y * hC.y);
        f[1][3] = pack_bf2(hD.x * hD.x, hD.y * hD.y);
        f[2][0] = pack_bf2(aA.x * hA.x, aA.y * hA.y);
        f[2][1] = pack_bf2(aB.x * hB.x, aB.y * hB.y);
        f[2][2] = pack_bf2(aC.x * hC.x, aC.y * hC.y);
        f[2][3] = pack_bf2(aD.x * hD.x, aD.y * hD.y);

        uint32_t bfr[3][2];
#pragma unroll
        for (int nt = 0; nt < 3; nt++) {
            int br = nt * 8 + (lane & 7);
            int bk = k0 + ((lane >> 3) & 1) * 8;
            uint32_t addr = w2base + (uint32_t)(br * 1040 + bk * 2);
            asm volatile("ldmatrix.sync.aligned.m8n8.x2.shared.b16 {%0,%1}, [%2];"
                         : "=r"(bfr[nt][0]), "=r"(bfr[nt][1])
                         : "r"(addr));
        }
#pragma unroll
        for (int s = 0; s < 3; s++)
#pragma unroll
            for (int nt = 0; nt < 3; nt++) {
                asm volatile(
                    "mma.sync.aligned.m16n8k16.row.col.f32.bf16.bf16.f32 "
                    "{%0,%1,%2,%3}, {%4,%5,%6,%7}, {%8,%9}, {%0,%1,%2,%3};"
                    : "+f"(acc[s][nt][0]), "+f"(acc[s][nt][1]),
                      "+f"(acc[s][nt][2]), "+f"(acc[s][nt][3])
                    : "r"(f[s][0]), "r"(f[s][1]), "r"(f[s][2]), "r"(f[s][3]),
                      "r"(bfr[nt][0]), "r"(bfr[nt][1]));
            }
    }

    // ---- cross-K reduction: wk=1 dumps, wk=0 adds ----
    __syncthreads();   // sW2 reads done (sred shares the block, not sW2 space)
    if (wk == 1) {
        float* dst = sred + (wr * 32 + lane) * 36;
#pragma unroll
        for (int s = 0; s < 3; s++)
#pragma unroll
            for (int nt = 0; nt < 3; nt++)
#pragma unroll
                for (int k = 0; k < 4; k++)
                    dst[s * 12 + nt * 4 + k] = acc[s][nt][k];
    }
    __syncthreads();
    if (wk == 0) {
        const float* src = sred + (wr * 32 + lane) * 36;
#pragma unroll
        for (int s = 0; s < 3; s++)
#pragma unroll
            for (int nt = 0; nt < 3; nt++)
#pragma unroll
                for (int k = 0; k < 4; k++)
                    acc[s][nt][k] += src[s * 12 + nt * 4 + k];

        // ---- epilogue ----
        int rg0 = row0 + wr * 16 + (lane >> 2);
#pragma unroll
        for (int nt = 0; nt < 3; nt++) {
            int c0 = nt * 8 + (lane & 3) * 2;
#pragma unroll
            for (int half = 0; half < 2; half++) {
                int rg = rg0 + half * 8;
                float s1a = acc[0][nt][half * 2],     s1b = acc[0][nt][half * 2 + 1];
                float s2a = acc[1][nt][half * 2],     s2b = acc[1][nt][half * 2 + 1];
                float s3a = acc[2][nt][half * 2],     s3b = acc[2][nt][half * 2 + 1];
                float va = s3a * rsqrtf(fmaxf(s1a, EPSV)) * rsqrtf(fmaxf(s2a, EPSV));
                float vb = s3b * rsqrtf(fmaxf(s1b, EPSV)) * rsqrtf(fmaxf(s2b, EPSV));
                if (c0 < PP) {
                    out[(size_t)rg * PP + c0] = va;
                    if (dup) out[(size_t)BB * TT * PP + (size_t)rg * PP + c0] = va;
                }
                if (c0 + 1 < PP) {
                    out[(size_t)rg * PP + c0 + 1] = vb;
                    if (dup) out[(size_t)BB * TT * PP + (size_t)rg * PP + c0 + 1] = vb;
                }
            }
        }
    }
}

// ---------------------------------------------------------------------------
extern "C" void kernel_launch(void* const* d_in, const int* in_sizes, int n_in,
                              void* d_out, int out_size) {
    const float* inp_a = (const float*)d_in[0];
    const float* inp_b = (const float*)d_in[1];
    const float* W     = (const float*)d_in[2];
    float* out = (float*)d_out;
    int dup = (out_size >= 2 * BB * TT * PP) ? 1 : 0;

    void *p_nbn_bf, *p_nbnT_bf, *p_nanT_bf, *p_alphaTb, *p_colpart, *p_hmean_bf;
    cudaGetSymbolAddress(&p_nbn_bf, g_nbn_bf);
    cudaGetSymbolAddress(&p_nbnT_bf, g_nbnT_bf);
    cudaGetSymbolAddress(&p_nanT_bf, g_nanT_bf);
    cudaGetSymbolAddress(&p_alphaTb, g_alphaTb);
    cudaGetSymbolAddress(&p_colpart, g_colpart);
    cudaGetSymbolAddress(&p_hmean_bf, g_hmean_bf);

    // 1) normalize + transpose -> bf16
    k_normT<<<dim3(TT / 16, BB, 2), 256>>>(inp_a, inp_b);

    // 2) GEMM1: alphaTb[e][d] = bf16( sum_t nbnT[d,t]*nanT[e,t] ) + colpart sumsq
    k_gemm_bf16<<<dim3(4, 4, BB), 256>>>(
        (const __nv_bfloat16*)p_nbnT_bf, TT, (size_t)DD * TT,
        (const __nv_bfloat16*)p_nanT_bf, TT, (size_t)DD * TT,
        (__nv_bfloat16*)p_alphaTb, (size_t)DD * DD,
        (float*)p_colpart, TT, 1);

    // 3) GEMM2: hmean_bf[t][e] = bf16( (sum_d alphaTb[e,d]*nbn[t,d]) * invcol[e] )
    k_gemm_bf16<<<dim3(4, 2, BB), 256>>>(
        (const __nv_bfloat16*)p_alphaTb, DD, (size_t)DD * DD,
        (const __nv_bfloat16*)p_nbn_bf, DD, (size_t)TT * DD,
        (__nv_bfloat16*)p_hmean_bf, (size_t)TT * DD,
        (float*)p_colpart, DD, 2);

    // 4) perspective scores via tensor cores, K-split x2
    k_persp3<<<BB * TT / 64, 256>>>(inp_a, W, out, dup);
}